// round 7
// baseline (speedup 1.0000x reference)
#include <cuda_runtime.h>
#include <math.h>

#define T_STEPS 2048
#define BATCH   16
#define DDIM    1024
#define NPROJ   448           // 384 (kv) + 64 (q)
#define NOUT    (T_STEPS*BATCH*64)
#define MSIZE   (3*BATCH*64*64)
#define NSCAN   16
#define NCTA    148
#define NGEMM   (NCTA-NSCAN)
#define NRB     512           // row blocks of 64 proj rows (= 4 timesteps)
#define NTILES  (NRB*7)

__device__ float g_proj[(size_t)T_STEPS * BATCH * NPROJ];
__device__ int   g_cnt[NRB];

typedef unsigned long long ull;

__device__ __forceinline__ ull pk2(float lo, float hi) {
    ull r; asm("mov.b64 %0,{%1,%2};" : "=l"(r) : "f"(lo), "f"(hi)); return r;
}
__device__ __forceinline__ void upk2(ull v, float& a, float& b) {
    asm("mov.b64 {%0,%1},%2;" : "=f"(a), "=f"(b) : "l"(v));
}
__device__ __forceinline__ ull f2fma(ull a, ull b, ull c) {
    ull d; asm("fma.rn.f32x2 %0,%1,%2,%3;" : "=l"(d) : "l"(a), "l"(b), "l"(c)); return d;
}
__device__ __forceinline__ ull f2mul(ull a, ull b) {
    ull d; asm("mul.rn.f32x2 %0,%1,%2;" : "=l"(d) : "l"(a), "l"(b)); return d;
}
__device__ __forceinline__ int ldacq(const int* p) {
    int v; asm volatile("ld.acquire.gpu.global.b32 %0,[%1];" : "=r"(v) : "l"(p) : "memory"); return v;
}
__device__ __forceinline__ void redrel(int* p) {
    asm volatile("red.release.gpu.global.add.s32 [%0],1;" :: "l"(p) : "memory");
}
__device__ __forceinline__ unsigned smem_u32(const void* p) {
    unsigned a;
    asm("{.reg .u64 t; cvta.to.shared.u64 t,%1; cvt.u32.u64 %0,t;}" : "=r"(a) : "l"(p));
    return a;
}
__device__ __forceinline__ void cp16(unsigned dst, const void* src) {
    asm volatile("cp.async.cg.shared.global [%0],[%1],16;" :: "r"(dst), "l"(src) : "memory");
}
__device__ __forceinline__ void cp_commit() {
    asm volatile("cp.async.commit_group;" ::: "memory");
}
__device__ __forceinline__ void cp_wait1() {
    asm volatile("cp.async.wait_group 1;" ::: "memory");
}
__device__ __forceinline__ float sigm(float x) {
    return __fdividef(1.0f, 1.0f + __expf(-x));
}

__global__ void zero_cnt() { if (threadIdx.x < NRB) g_cnt[threadIdx.x] = 0; }

struct GemmS { float Xs[16][64]; float Ws[16][64]; };
struct ScanS {
    float raw[8][NPROJ];       // 8-deep ring of projection rows
    float kn[4][3][64];        // normalized k, 4-deep
    float cgkn[4][3][128];     // {cg[2p],cg[2p+1],kn[2p],kn[2p+1]}, 4-deep
    float rgdl[2][3][128];     // {rg[2p],rg[2p+1],dl[2p],dl[2p+1]}, 2-deep
};

// ===========================================================================
// Variant A: 768-thread blocks. Scan has 6 warps/SMSP (reg cap 85 — chosen at
// launch ONLY if ptxas did not spill; host checks localSizeBytes).
// ===========================================================================
__global__ __launch_bounds__(768, 1) void fused768(
    const float* __restrict__ X,
    const float* __restrict__ Wkv,
    const float* __restrict__ Wq,
    const float* __restrict__ Mi,
    const float* __restrict__ Bg,
    float* __restrict__ out,
    int write_M)
{
    __shared__ __align__(16) union { GemmS g; ScanS s; } sm;
    const int tid = threadIdx.x;

    if (blockIdx.x >= NSCAN) {
        // ---- GEMM producer: 512 compute threads, 2x4 micro-tile (~35 regs)
        const int tx = tid & 15;
        const int ty = tid >> 4;          // 0..31 for tid<512
        const bool ldx = (tid < 256);
        const bool ldw = (tid >= 256 && tid < 512);
        const int lr = (tid & 255) >> 2;
        const int lc = (tid & 3) * 4;

        for (int tt = (int)blockIdx.x - NSCAN; tt < NTILES; tt += NGEMM) {
            const int rb = tt / 7, cb = tt % 7;
            const int bm = rb * 64, bn = cb * 64;

            float acc[2][4];
#pragma unroll
            for (int a = 0; a < 2; a++)
#pragma unroll
                for (int c = 0; c < 4; c++) acc[a][c] = 0.f;

            const float* xrow = X + (size_t)(bm + lr) * DDIM + lc;
            const int wr = bn + lr;
            const float* wrow = (wr < 384 ? Wkv + (size_t)wr * DDIM
                                          : Wq + (size_t)(wr - 384) * DDIM) + lc;

            for (int k0 = 0; k0 < DDIM; k0 += 16) {
                if (ldx) {
                    float4 xv = *(const float4*)(xrow + k0);
                    sm.g.Xs[lc + 0][lr] = xv.x; sm.g.Xs[lc + 1][lr] = xv.y;
                    sm.g.Xs[lc + 2][lr] = xv.z; sm.g.Xs[lc + 3][lr] = xv.w;
                } else if (ldw) {
                    float4 wv = *(const float4*)(wrow + k0);
                    sm.g.Ws[lc + 0][lr] = wv.x; sm.g.Ws[lc + 1][lr] = wv.y;
                    sm.g.Ws[lc + 2][lr] = wv.z; sm.g.Ws[lc + 3][lr] = wv.w;
                }
                __syncthreads();
                if (tid < 512) {
#pragma unroll
                    for (int kk = 0; kk < 16; kk++) {
                        float2 xr2 = *(const float2*)&sm.g.Xs[kk][ty * 2];
                        float4 wr4 = *(const float4*)&sm.g.Ws[kk][tx * 4];
                        acc[0][0] = fmaf(xr2.x, wr4.x, acc[0][0]);
                        acc[0][1] = fmaf(xr2.x, wr4.y, acc[0][1]);
                        acc[0][2] = fmaf(xr2.x, wr4.z, acc[0][2]);
                        acc[0][3] = fmaf(xr2.x, wr4.w, acc[0][3]);
                        acc[1][0] = fmaf(xr2.y, wr4.x, acc[1][0]);
                        acc[1][1] = fmaf(xr2.y, wr4.y, acc[1][1]);
                        acc[1][2] = fmaf(xr2.y, wr4.z, acc[1][2]);
                        acc[1][3] = fmaf(xr2.y, wr4.w, acc[1][3]);
                    }
                }
                __syncthreads();
            }
            if (tid < 512) {
#pragma unroll
                for (int a = 0; a < 2; a++) {
                    float4 o = {acc[a][0], acc[a][1], acc[a][2], acc[a][3]};
                    *(float4*)&g_proj[(size_t)(bm + ty * 2 + a) * NPROJ + bn + tx * 4] = o;
                }
            }
            __syncthreads();
            if (tid == 0) redrel(&g_cnt[rb]);
        }
        return;
    }

    // ---------------- Scan consumer (768 threads, 1 barrier/step) ----------
    const int b    = blockIdx.x;
    const int g    = tid >> 8;           // 0..2
    const int r    = tid & 255;
    const int i    = r >> 2;             // row 0..63
    const int h    = r & 3;              // column quarter (16 cols)
    const int gm1  = (g + 2) % 3;
    const int wid  = tid >> 5, lane = tid & 31;
    ScanS& S = sm.s;

    ull Mr2[8], MTr2[8];
    {
        const float* M0 = Mi + ((size_t)(g * BATCH + b)) * 4096;
#pragma unroll
        for (int j = 0; j < 8; j++) {
            float2 a = *(const float2*)&M0[i * 64 + 16 * h + 2 * j];
            Mr2[j]  = pk2(a.x, a.y);
            MTr2[j] = pk2(M0[(16 * h + 2 * j) * 64 + i],
                          M0[(16 * h + 2 * j + 1) * 64 + i]);
        }
    }
    const float bgm = Bg[gm1 * 64 + i];

    const bool pf   = (tid >= 640 && tid < 752);  // warps 20-23 (g=2 tail)
    const int  pidx = tid - 640;
    const bool knw  = (wid >= 16 && wid < 19);    // kn-next on g=2 warps
    const int  kw   = wid - 16;
    int verified = 0;                              // highest rowblock confirmed

    // Prologue: stage rows 0..2, issue row 3; then kn[0].
    if (pf) {
        while (ldacq(&g_cnt[0]) < 7) __nanosleep(64);
#pragma unroll
        for (int rr = 0; rr < 3; rr++) {
            cp16(smem_u32(&S.raw[rr][pidx * 4]),
                 g_proj + (size_t)(rr * BATCH + b) * NPROJ + pidx * 4);
            cp_commit();
        }
        cp16(smem_u32(&S.raw[3][pidx * 4]),
             g_proj + (size_t)(3 * BATCH + b) * NPROJ + pidx * 4);
        cp_commit();
        cp_wait1();    // rows 0..2 complete, row 3 pending
    }
    __syncthreads();
    if (knw) {
        float a0 = S.raw[0][kw * 128 + lane];
        float a1 = S.raw[0][kw * 128 + 32 + lane];
        float ssq = a0 * a0 + a1 * a1;
#pragma unroll
        for (int o = 16; o; o >>= 1) ssq += __shfl_xor_sync(0xffffffffu, ssq, o);
        float inv = __fdividef(1.0f, sqrtf(ssq) + 1e-6f);
        float k0 = a0 * inv, k1 = a1 * inv;
        S.kn[0][kw][lane]      = k0;
        S.kn[0][kw][lane + 32] = k1;
        S.cgkn[0][kw][4 * (lane >> 1) + 2 + (lane & 1)]        = k0;
        S.cgkn[0][kw][4 * ((lane + 32) >> 1) + 2 + (lane & 1)] = k1;
    }
    __syncthreads();

    for (int t = 0; t < T_STEPS; t++) {
        const int cur = t & 7, b4 = t & 3, b2 = t & 1;
        const int nb4 = (t + 1) & 3;

        // ======== region A (pre-barrier) ========
        ull rp = 0ull, ap = 0ull, cp = 0ull;
        {
            const ulonglong2* kg = (const ulonglong2*)(S.kn[b4][g]   + 16 * h);
            const ulonglong2* km = (const ulonglong2*)(S.kn[b4][gm1] + 16 * h);
#pragma unroll
            for (int j4 = 0; j4 < 4; j4++) {
                ulonglong2 kv  = kg[j4];
                ulonglong2 kmv = km[j4];
                rp = f2fma(Mr2[2 * j4],     kv.x,  rp);
                rp = f2fma(Mr2[2 * j4 + 1], kv.y,  rp);
                ap = f2fma(Mr2[2 * j4],     kmv.x, ap);
                ap = f2fma(Mr2[2 * j4 + 1], kmv.y, ap);
                cp = f2fma(MTr2[2 * j4],     kmv.x, cp);
                cp = f2fma(MTr2[2 * j4 + 1], kmv.y, cp);
            }
        }
        const int pi = 4 * (i >> 1);
        {
            float rlo, rhi, alo, ahi, clo, chi;
            upk2(rp, rlo, rhi); upk2(ap, alo, ahi); upk2(cp, clo, chi);
            float rpart = rlo + rhi, apart = alo + ahi, cpart = clo + chi;
            rpart += __shfl_xor_sync(0xffffffffu, rpart, 1);
            apart += __shfl_xor_sync(0xffffffffu, apart, 1);
            cpart += __shfl_xor_sync(0xffffffffu, cpart, 1);
            rpart += __shfl_xor_sync(0xffffffffu, rpart, 2);
            apart += __shfl_xor_sync(0xffffffffu, apart, 2);
            cpart += __shfl_xor_sync(0xffffffffu, cpart, 2);
            if (h == 0) {
                S.rgdl[b2][gm1][pi + (i & 1)]     = sigm(apart + bgm);
                S.rgdl[b2][g]  [pi + 2 + (i & 1)] = S.raw[cur][g * 128 + 64 + i] - rpart;
            } else if (h == 1) {
                S.cgkn[b4][gm1][pi + (i & 1)]     = sigm(cpart + bgm);
            }
        }

        // kn for row t+1 (g=2 warps 16-18; row t+1 complete + visible)
        if (knw && t + 1 < T_STEPS) {
            float a0 = S.raw[(t + 1) & 7][kw * 128 + lane];
            float a1 = S.raw[(t + 1) & 7][kw * 128 + 32 + lane];
            float ssq = a0 * a0 + a1 * a1;
#pragma unroll
            for (int o = 16; o; o >>= 1) ssq += __shfl_xor_sync(0xffffffffu, ssq, o);
            float inv = __fdividef(1.0f, sqrtf(ssq) + 1e-6f);
            float k0 = a0 * inv, k1 = a1 * inv;
            S.kn[nb4][kw][lane]      = k0;
            S.kn[nb4][kw][lane + 32] = k1;
            S.cgkn[nb4][kw][4 * (lane >> 1) + 2 + (lane & 1)]        = k0;
            S.cgkn[nb4][kw][4 * ((lane + 32) >> 1) + 2 + (lane & 1)] = k1;
        }

        // prefetch row t+4 (flag poll cached per rowblock)
        if (pf) {
            const int t4 = t + 4;
            if (t4 < T_STEPS) {
                const int r4 = t4 * BATCH + b;
                const int rb4 = r4 >> 6;
                if (rb4 > verified) {
                    while (ldacq(&g_cnt[rb4]) < 7) __nanosleep(64);
                    verified = rb4;
                }
                cp16(smem_u32(&S.raw[t4 & 7][pidx * 4]),
                     g_proj + (size_t)r4 * NPROJ + pidx * 4);
            }
            cp_commit();
            cp_wait1();
        }
        __syncthreads();   // the ONE barrier per step

        // ======== region B (post-barrier): gated update + output ========
        {
            const float cg_i = S.cgkn[b4][g][pi + (i & 1)];
            const float kn_i = S.cgkn[b4][g][pi + 2 + (i & 1)];
            const float rg_i = S.rgdl[b2][g][pi + (i & 1)];
            const float d_i  = S.rgdl[b2][g][pi + 2 + (i & 1)];
            const ull rgd = pk2(rg_i, rg_i), cgd = pk2(cg_i, cg_i);
            const ull dd  = pk2(d_i,  d_i),  knd = pk2(kn_i, kn_i);
            const ulonglong2* ck = (const ulonglong2*)(S.cgkn[b4][g] + 32 * h);
            const ulonglong2* rd = (const ulonglong2*)(S.rgdl[b2][g] + 32 * h);
#pragma unroll
            for (int j = 0; j < 8; j++) {
                ulonglong2 a  = ck[j];   // {cg pair, kn pair}
                ulonglong2 bq = rd[j];   // {rg pair, dl pair}
                Mr2[j]  = f2fma(f2mul(Mr2[j],  a.x),  rgd, f2mul(a.y,  dd));
                MTr2[j] = f2fma(f2mul(MTr2[j], bq.x), cgd, f2mul(bq.y, knd));
            }
        }
        if (!g) {
            ull s0 = 0ull, s1 = 0ull;      // 2 accums: halve chain depth
            const ulonglong2* q2 = (const ulonglong2*)(S.raw[cur] + 384 + 16 * h);
#pragma unroll
            for (int j4 = 0; j4 < 4; j4++) {
                ulonglong2 q = q2[j4];
                s0 = f2fma(Mr2[2 * j4],     q.x, s0);
                s1 = f2fma(Mr2[2 * j4 + 1], q.y, s1);
            }
            float slo, shi, tlo, thi;
            upk2(s0, slo, shi); upk2(s1, tlo, thi);
            float s = (slo + shi) + (tlo + thi);
            s += __shfl_xor_sync(0xffffffffu, s, 1);
            s += __shfl_xor_sync(0xffffffffu, s, 2);
            if (!h) out[((size_t)t * BATCH + b) * 64 + i] = s * sigm(s);
        }
    }

    if (write_M) {
        float* Mo = out + NOUT + ((size_t)(g * BATCH + b)) * 4096
                    + (size_t)i * 64 + 16 * h;
#pragma unroll
        for (int j = 0; j < 8; j++) {
            float a, c; upk2(Mr2[j], a, c);
            Mo[2 * j] = a; Mo[2 * j + 1] = c;
        }
    }
}

// ===========================================================================
// Variant B: proven R6 kernel (384 threads) — fallback if variant A spills.
// ===========================================================================
__global__ __launch_bounds__(384, 1) void fused384(
    const float* __restrict__ X,
    const float* __restrict__ Wkv,
    const float* __restrict__ Wq,
    const float* __restrict__ Mi,
    const float* __restrict__ Bg,
    float* __restrict__ out,
    int write_M)
{
    __shared__ __align__(16) union { GemmS g; ScanS s; } sm;
    const int tid = threadIdx.x;

    if (blockIdx.x >= NSCAN) {
        const int tx = tid & 15;
        const int ty = tid >> 4;
        const int lr = tid >> 2;
        const int lc = (tid & 3) * 4;

        for (int tt = (int)blockIdx.x - NSCAN; tt < NTILES; tt += NGEMM) {
            const int rb = tt / 7, cb = tt % 7;
            const int bm = rb * 64, bn = cb * 64;

            float acc[4][4];
#pragma unroll
            for (int a = 0; a < 4; a++)
#pragma unroll
                for (int c = 0; c < 4; c++) acc[a][c] = 0.f;

            const float* xrow = X + (size_t)(bm + lr) * DDIM + lc;
            const int wr = bn + lr;
            const float* wrow = (wr < 384 ? Wkv + (size_t)wr * DDIM
                                          : Wq + (size_t)(wr - 384) * DDIM) + lc;

            for (int k0 = 0; k0 < DDIM; k0 += 16) {
                if (tid < 256) {
                    float4 xv = *(const float4*)(xrow + k0);
                    float4 wv = *(const float4*)(wrow + k0);
                    sm.g.Xs[lc + 0][lr] = xv.x; sm.g.Xs[lc + 1][lr] = xv.y;
                    sm.g.Xs[lc + 2][lr] = xv.z; sm.g.Xs[lc + 3][lr] = xv.w;
                    sm.g.Ws[lc + 0][lr] = wv.x; sm.g.Ws[lc + 1][lr] = wv.y;
                    sm.g.Ws[lc + 2][lr] = wv.z; sm.g.Ws[lc + 3][lr] = wv.w;
                }
                __syncthreads();
                if (tid < 256) {
#pragma unroll
                    for (int kk = 0; kk < 16; kk++) {
                        float4 xr4 = *(const float4*)&sm.g.Xs[kk][ty * 4];
                        float4 wr4 = *(const float4*)&sm.g.Ws[kk][tx * 4];
                        float xa[4] = {xr4.x, xr4.y, xr4.z, xr4.w};
                        float wb[4] = {wr4.x, wr4.y, wr4.z, wr4.w};
#pragma unroll
                        for (int a = 0; a < 4; a++)
#pragma unroll
                            for (int c = 0; c < 4; c++)
                                acc[a][c] = fmaf(xa[a], wb[c], acc[a][c]);
                    }
                }
                __syncthreads();
            }
            if (tid < 256) {
#pragma unroll
                for (int a = 0; a < 4; a++) {
                    float4 o = {acc[a][0], acc[a][1], acc[a][2], acc[a][3]};
                    *(float4*)&g_proj[(size_t)(bm + ty * 4 + a) * NPROJ + bn + tx * 4] = o;
                }
            }
            __syncthreads();
            if (tid == 0) redrel(&g_cnt[rb]);
        }
        return;
    }

    const int b    = blockIdx.x;
    const int g    = tid >> 7;
    const int r    = tid & 127;
    const int i    = r >> 1;
    const int h    = tid & 1;
    const int gm1  = (g + 2) % 3;
    const int wid  = tid >> 5, lane = tid & 31;
    ScanS& S = sm.s;

    ull Mr2[16], MTr2[16];
    {
        const float* M0 = Mi + ((size_t)(g * BATCH + b)) * 4096;
#pragma unroll
        for (int j = 0; j < 16; j++) {
            float2 a = *(const float2*)&M0[i * 64 + 32 * h + 2 * j];
            Mr2[j]  = pk2(a.x, a.y);
            MTr2[j] = pk2(M0[(32 * h + 2 * j) * 64 + i],
                          M0[(32 * h + 2 * j + 1) * 64 + i]);
        }
    }
    const float bgm = Bg[gm1 * 64 + i];

    const bool pf = (tid >= 96 && tid < 208);
    const int  pidx = tid - 96;

    if (pf) {
        while (ldacq(&g_cnt[0]) < 7) __nanosleep(64);
#pragma unroll
        for (int rr = 0; rr < 3; rr++) {
            cp16(smem_u32(&S.raw[rr][pidx * 4]),
                 g_proj + (size_t)(rr * BATCH + b) * NPROJ + pidx * 4);
            cp_commit();
        }
        cp16(smem_u32(&S.raw[3][pidx * 4]),
             g_proj + (size_t)(3 * BATCH + b) * NPROJ + pidx * 4);
        cp_commit();
        cp_wait1();
    }
    __syncthreads();
    if (wid < 3) {
        float a0 = S.raw[0][wid * 128 + lane];
        float a1 = S.raw[0][wid * 128 + 32 + lane];
        float ssq = a0 * a0 + a1 * a1;
#pragma unroll
        for (int o = 16; o; o >>= 1) ssq += __shfl_xor_sync(0xffffffffu, ssq, o);
        float inv = __fdividef(1.0f, sqrtf(ssq) + 1e-6f);
        float k0 = a0 * inv, k1 = a1 * inv;
        S.kn[0][wid][lane]      = k0;
        S.kn[0][wid][lane + 32] = k1;
        S.cgkn[0][wid][4 * (lane >> 1) + 2 + (lane & 1)]        = k0;
        S.cgkn[0][wid][4 * ((lane + 32) >> 1) + 2 + (lane & 1)] = k1;
    }
    __syncthreads();

    for (int t = 0; t < T_STEPS; t++) {
        const int cur = t & 7, b4 = t & 3, b2 = t & 1;
        const int nb4 = (t + 1) & 3;

        ull rp = 0ull, ap = 0ull, cp = 0ull;
        {
            const ulonglong2* kg = (const ulonglong2*)(S.kn[b4][g]   + 32 * h);
            const ulonglong2* km = (const ulonglong2*)(S.kn[b4][gm1] + 32 * h);
#pragma unroll
            for (int j4 = 0; j4 < 8; j4++) {
                ulonglong2 kv  = kg[j4];
                ulonglong2 kmv = km[j4];
                rp = f2fma(Mr2[2 * j4],     kv.x,  rp);
                rp = f2fma(Mr2[2 * j4 + 1], kv.y,  rp);
                ap = f2fma(Mr2[2 * j4],     kmv.x, ap);
                ap = f2fma(Mr2[2 * j4 + 1], kmv.y, ap);
                cp = f2fma(MTr2[2 * j4],     kmv.x, cp);
                cp = f2fma(MTr2[2 * j4 + 1], kmv.y, cp);
            }
        }
        float rlo, rhi, alo, ahi, clo, chi;
        upk2(rp, rlo, rhi); upk2(ap, alo, ahi); upk2(cp, clo, chi);
        float rpart = rlo + rhi, apart = alo + ahi, cpart = clo + chi;
        rpart += __shfl_xor_sync(0xffffffffu, rpart, 1);
        apart += __shfl_xor_sync(0xffffffffu, apart, 1);
        cpart += __shfl_xor_sync(0xffffffffu, cpart, 1);
        const int pi = 4 * (i >> 1);
        if (!h) {
            S.rgdl[b2][gm1][pi + (i & 1)]     = sigm(apart + bgm);
            S.rgdl[b2][g]  [pi + 2 + (i & 1)] = S.raw[cur][g * 128 + 64 + i] - rpart;
        } else {
            S.cgkn[b4][gm1][pi + (i & 1)]     = sigm(cpart + bgm);
        }

        if (wid < 3 && t + 1 < T_STEPS) {
            float a0 = S.raw[(t + 1) & 7][wid * 128 + lane];
            float a1 = S.raw[(t + 1) & 7][wid * 128 + 32 + lane];
            float ssq = a0 * a0 + a1 * a1;
#pragma unroll
            for (int o = 16; o; o >>= 1) ssq += __shfl_xor_sync(0xffffffffu, ssq, o);
            float inv = __fdividef(1.0f, sqrtf(ssq) + 1e-6f);
            float k0 = a0 * inv, k1 = a1 * inv;
            S.kn[nb4][wid][lane]      = k0;
            S.kn[nb4][wid][lane + 32] = k1;
            S.cgkn[nb4][wid][4 * (lane >> 1) + 2 + (lane & 1)]        = k0;
            S.cgkn[nb4][wid][4 * ((lane + 32) >> 1) + 2 + (lane & 1)] = k1;
        }

        if (pf) {
            const int t4 = t + 4;
            if (t4 < T_STEPS) {
                const int r4 = t4 * BATCH + b;
                while (ldacq(&g_cnt[r4 >> 6]) < 7) __nanosleep(64);
                cp16(smem_u32(&S.raw[t4 & 7][pidx * 4]),
                     g_proj + (size_t)r4 * NPROJ + pidx * 4);
            }
            cp_commit();
            cp_wait1();
        }
        __syncthreads();

        const float cg_i = S.cgkn[b4][g][pi + (i & 1)];
        const float kn_i = S.cgkn[b4][g][pi + 2 + (i & 1)];
        const float rg_i = S.rgdl[b2][g][pi + (i & 1)];
        const float d_i  = S.rgdl[b2][g][pi + 2 + (i & 1)];
        const ull rgd = pk2(rg_i, rg_i), cgd = pk2(cg_i, cg_i);
        const ull dd  = pk2(d_i,  d_i),  knd = pk2(kn_i, kn_i);
        {
            const ulonglong2* ck = (const ulonglong2*)(S.cgkn[b4][g] + 64 * h);
            const ulonglong2* rd = (const ulonglong2*)(S.rgdl[b2][g] + 64 * h);
#pragma unroll
            for (int j = 0; j < 16; j++) {
                ulonglong2 a  = ck[j];
                ulonglong2 bq = rd[j];
                Mr2[j]  = f2fma(f2mul(Mr2[j],  a.x),  rgd, f2mul(a.y,  dd));
                MTr2[j] = f2fma(f2mul(MTr2[j], bq.x), cgd, f2mul(bq.y, knd));
            }
        }
        if (!g) {
            ull sq = 0ull;
            const ulonglong2* q2 = (const ulonglong2*)(S.raw[cur] + 384 + 32 * h);
#pragma unroll
            for (int j4 = 0; j4 < 8; j4++) {
                ulonglong2 q = q2[j4];
                sq = f2fma(Mr2[2 * j4],     q.x, sq);
                sq = f2fma(Mr2[2 * j4 + 1], q.y, sq);
            }
            float slo, shi; upk2(sq, slo, shi);
            float s = slo + shi;
            s += __shfl_xor_sync(0xffffffffu, s, 1);
            if (!h) out[((size_t)t * BATCH + b) * 64 + i] = s * sigm(s);
        }
    }

    if (write_M) {
        float* Mo = out + NOUT + ((size_t)(g * BATCH + b)) * 4096
                    + (size_t)i * 64 + 32 * h;
#pragma unroll
        for (int j = 0; j < 16; j++) {
            float a, c; upk2(Mr2[j], a, c);
            Mo[2 * j] = a; Mo[2 * j + 1] = c;
        }
    }
}

// ---------------------------------------------------------------------------
extern "C" void kernel_launch(void* const* d_in, const int* in_sizes, int n_in,
                              void* d_out, int out_size)
{
    const float *x = nullptr, *Mi = nullptr, *Wkv = nullptr,
                *Wq = nullptr, *Bg = nullptr;
    for (int idx = 0; idx < n_in; idx++) {
        switch (in_sizes[idx]) {
            case 33554432: x   = (const float*)d_in[idx]; break;
            case 196608:   Mi  = (const float*)d_in[idx]; break;
            case 393216:   Wkv = (const float*)d_in[idx]; break;
            case 65536:    Wq  = (const float*)d_in[idx]; break;
            case 192:      Bg  = (const float*)d_in[idx]; break;
        }
    }
    if (!x || !Mi || !Wkv || !Wq || !Bg) {
        x   = (const float*)d_in[0];
        Mi  = (const float*)d_in[1];
        Wkv = (const float*)d_in[2];
        Wq  = (const float*)d_in[3];
        Bg  = (const float*)d_in[4];
    }

    const int write_M = (out_size >= NOUT + MSIZE) ? 1 : 0;

    // Hedge: use the 6-warp/SMSP variant only if ptxas kept it spill-free.
    cudaFuncAttributes attr;
    bool use768 = false;
    if (cudaFuncGetAttributes(&attr, (const void*)fused768) == cudaSuccess)
        use768 = (attr.localSizeBytes == 0);

    zero_cnt<<<1, 512>>>();
    if (use768)
        fused768<<<NCTA, 768>>>(x, Wkv, Wq, Mi, Bg, (float*)d_out, write_M);
    else
        fused384<<<NCTA, 384>>>(x, Wkv, Wq, Mi, Bg, (float*)d_out, write_M);
}

// round 8
// speedup vs baseline: 2.8917x; 2.8917x over previous
#include <cuda_runtime.h>
#include <math.h>

#define T_STEPS 2048
#define BATCH   16
#define DDIM    1024
#define NPROJ   448           // 384 (kv) + 64 (q)
#define NOUT    (T_STEPS*BATCH*64)
#define MSIZE   (3*BATCH*64*64)
#define NSCAN   16
#define NCTA    148
#define NGEMM   (NCTA-NSCAN)
#define NRB     512           // row blocks of 64 proj rows (= 4 timesteps)
#define NTILES  (NRB*7)

__device__ float g_proj[(size_t)T_STEPS * BATCH * NPROJ];
__device__ int   g_cnt[NRB];

typedef unsigned long long ull;

__device__ __forceinline__ ull pk2(float lo, float hi) {
    ull r; asm("mov.b64 %0,{%1,%2};" : "=l"(r) : "f"(lo), "f"(hi)); return r;
}
__device__ __forceinline__ void upk2(ull v, float& a, float& b) {
    asm("mov.b64 {%0,%1},%2;" : "=f"(a), "=f"(b) : "l"(v));
}
__device__ __forceinline__ ull f2fma(ull a, ull b, ull c) {
    ull d; asm("fma.rn.f32x2 %0,%1,%2,%3;" : "=l"(d) : "l"(a), "l"(b), "l"(c)); return d;
}
__device__ __forceinline__ ull f2mul(ull a, ull b) {
    ull d; asm("mul.rn.f32x2 %0,%1,%2;" : "=l"(d) : "l"(a), "l"(b)); return d;
}
__device__ __forceinline__ int ldacq(const int* p) {
    int v; asm volatile("ld.acquire.gpu.global.b32 %0,[%1];" : "=r"(v) : "l"(p) : "memory"); return v;
}
__device__ __forceinline__ void redrel(int* p) {
    asm volatile("red.release.gpu.global.add.s32 [%0],1;" :: "l"(p) : "memory");
}
__device__ __forceinline__ unsigned smem_u32(const void* p) {
    unsigned a;
    asm("{.reg .u64 t; cvta.to.shared.u64 t,%1; cvt.u32.u64 %0,t;}" : "=r"(a) : "l"(p));
    return a;
}
__device__ __forceinline__ void cp16(unsigned dst, const void* src) {
    asm volatile("cp.async.cg.shared.global [%0],[%1],16;" :: "r"(dst), "l"(src) : "memory");
}
__device__ __forceinline__ void cp_commit() {
    asm volatile("cp.async.commit_group;" ::: "memory");
}
__device__ __forceinline__ void cp_wait1() {
    asm volatile("cp.async.wait_group 1;" ::: "memory");
}
__device__ __forceinline__ float sigm(float x) {
    return __fdividef(1.0f, 1.0f + __expf(-x));
}

__global__ void zero_cnt() { if (threadIdx.x < NRB) g_cnt[threadIdx.x] = 0; }

struct GemmS { float Xs[16][64]; float Ws[16][64]; };
struct ScanS {
    float raw[8][NPROJ];       // 8-deep ring of projection rows
    float kn[4][3][64];        // normalized k, 4-deep
    float cgkn[4][3][128];     // {cg[2p],cg[2p+1],kn[2p],kn[2p+1]}, 4-deep
    float rgdl[2][3][128];     // {rg[2p],rg[2p+1],dl[2p],dl[2p+1]}, 2-deep
};

// ===========================================================================
// Shared GEMM producer body (256 compute threads, 4x4 micro-tile — proven).
// ===========================================================================
template <int BLK>
__device__ __forceinline__ void gemm_body(
    GemmS& G, int tid, int bx,
    const float* __restrict__ X, const float* __restrict__ Wkv,
    const float* __restrict__ Wq)
{
    const int tx = tid & 15;
    const int ty = tid >> 4;          // valid for tid<256
    const int lr = tid >> 2;
    const int lc = (tid & 3) * 4;

    for (int tt = bx - NSCAN; tt < NTILES; tt += NGEMM) {
        const int rb = tt / 7, cb = tt % 7;
        const int bm = rb * 64, bn = cb * 64;

        float acc[4][4];
#pragma unroll
        for (int a = 0; a < 4; a++)
#pragma unroll
            for (int c = 0; c < 4; c++) acc[a][c] = 0.f;

        const float* xrow = X + (size_t)(bm + lr) * DDIM + lc;
        const int wr = bn + lr;
        const float* wrow = (wr < 384 ? Wkv + (size_t)wr * DDIM
                                      : Wq + (size_t)(wr - 384) * DDIM) + lc;

        for (int k0 = 0; k0 < DDIM; k0 += 16) {
            if (tid < 256) {
                float4 xv = *(const float4*)(xrow + k0);
                float4 wv = *(const float4*)(wrow + k0);
                G.Xs[lc + 0][lr] = xv.x; G.Xs[lc + 1][lr] = xv.y;
                G.Xs[lc + 2][lr] = xv.z; G.Xs[lc + 3][lr] = xv.w;
                G.Ws[lc + 0][lr] = wv.x; G.Ws[lc + 1][lr] = wv.y;
                G.Ws[lc + 2][lr] = wv.z; G.Ws[lc + 3][lr] = wv.w;
            }
            __syncthreads();
            if (tid < 256) {
#pragma unroll
                for (int kk = 0; kk < 16; kk++) {
                    float4 xr4 = *(const float4*)&G.Xs[kk][ty * 4];
                    float4 wr4 = *(const float4*)&G.Ws[kk][tx * 4];
                    float xa[4] = {xr4.x, xr4.y, xr4.z, xr4.w};
                    float wb[4] = {wr4.x, wr4.y, wr4.z, wr4.w};
#pragma unroll
                    for (int a = 0; a < 4; a++)
#pragma unroll
                        for (int c = 0; c < 4; c++)
                            acc[a][c] = fmaf(xa[a], wb[c], acc[a][c]);
                }
            }
            __syncthreads();
        }
        if (tid < 256) {
#pragma unroll
            for (int a = 0; a < 4; a++) {
                float4 o = {acc[a][0], acc[a][1], acc[a][2], acc[a][3]};
                *(float4*)&g_proj[(size_t)(bm + ty * 4 + a) * NPROJ + bn + tx * 4] = o;
            }
        }
        __syncthreads();
        if (tid == 0) redrel(&g_cnt[rb]);
    }
}

// ===========================================================================
// Variant A: 384 threads (proven envelope), rebalanced roles:
//   warps 0-3 (g=0): dots+gates+q-dot
//   warps 4-7 (g=1): dots+gates+prefetch (112 threads, flag-poll cached)
//   warps 8-10(g=2): dots+gates+kn-next
//   warp 11  (g=2): dots+gates only
// ===========================================================================
__global__ __launch_bounds__(384, 1) void fused384(
    const float* __restrict__ X,
    const float* __restrict__ Wkv,
    const float* __restrict__ Wq,
    const float* __restrict__ Mi,
    const float* __restrict__ Bg,
    float* __restrict__ out,
    int write_M)
{
    __shared__ __align__(16) union { GemmS g; ScanS s; } sm;
    const int tid = threadIdx.x;

    if (blockIdx.x >= NSCAN) {
        gemm_body<384>(sm.g, tid, (int)blockIdx.x, X, Wkv, Wq);
        return;
    }

    const int b    = blockIdx.x;
    const int g    = tid >> 7;
    const int r    = tid & 127;
    const int i    = r >> 1;
    const int h    = tid & 1;
    const int gm1  = (g + 2) % 3;
    const int wid  = tid >> 5, lane = tid & 31;
    ScanS& S = sm.s;

    ull Mr2[16], MTr2[16];
    {
        const float* M0 = Mi + ((size_t)(g * BATCH + b)) * 4096;
#pragma unroll
        for (int j = 0; j < 16; j++) {
            float2 a = *(const float2*)&M0[i * 64 + 32 * h + 2 * j];
            Mr2[j]  = pk2(a.x, a.y);
            MTr2[j] = pk2(M0[(32 * h + 2 * j) * 64 + i],
                          M0[(32 * h + 2 * j + 1) * 64 + i]);
        }
    }
    const float bgm = Bg[gm1 * 64 + i];

    const bool pf   = (tid >= 128 && tid < 240);  // warps 4-7 (g=1)
    const int  pidx = tid - 128;
    const bool knw  = (wid >= 8 && wid < 11);     // warps 8-10 (g=2)
    const int  kw   = wid - 8;
    int verified = 0;

    if (pf) {
        while (ldacq(&g_cnt[0]) < 7) __nanosleep(64);
#pragma unroll
        for (int rr = 0; rr < 3; rr++) {
            cp16(smem_u32(&S.raw[rr][pidx * 4]),
                 g_proj + (size_t)(rr * BATCH + b) * NPROJ + pidx * 4);
            cp_commit();
        }
        cp16(smem_u32(&S.raw[3][pidx * 4]),
             g_proj + (size_t)(3 * BATCH + b) * NPROJ + pidx * 4);
        cp_commit();
        cp_wait1();    // rows 0..2 complete, row 3 pending
    }
    __syncthreads();
    if (knw) {         // kn for row 0
        float a0 = S.raw[0][kw * 128 + lane];
        float a1 = S.raw[0][kw * 128 + 32 + lane];
        float ssq = a0 * a0 + a1 * a1;
#pragma unroll
        for (int o = 16; o; o >>= 1) ssq += __shfl_xor_sync(0xffffffffu, ssq, o);
        float inv = __fdividef(1.0f, sqrtf(ssq) + 1e-6f);
        float k0 = a0 * inv, k1 = a1 * inv;
        S.kn[0][kw][lane]      = k0;
        S.kn[0][kw][lane + 32] = k1;
        S.cgkn[0][kw][4 * (lane >> 1) + 2 + (lane & 1)]        = k0;
        S.cgkn[0][kw][4 * ((lane + 32) >> 1) + 2 + (lane & 1)] = k1;
    }
    __syncthreads();

    for (int t = 0; t < T_STEPS; t++) {
        const int cur = t & 7, b4 = t & 3, b2 = t & 1;
        const int nb4 = (t + 1) & 3;

        // ---- region A: dots + gates ----
        ull rp = 0ull, ap = 0ull, cp = 0ull;
        {
            const ulonglong2* kg = (const ulonglong2*)(S.kn[b4][g]   + 32 * h);
            const ulonglong2* km = (const ulonglong2*)(S.kn[b4][gm1] + 32 * h);
#pragma unroll
            for (int j4 = 0; j4 < 8; j4++) {
                ulonglong2 kv  = kg[j4];
                ulonglong2 kmv = km[j4];
                rp = f2fma(Mr2[2 * j4],     kv.x,  rp);
                rp = f2fma(Mr2[2 * j4 + 1], kv.y,  rp);
                ap = f2fma(Mr2[2 * j4],     kmv.x, ap);
                ap = f2fma(Mr2[2 * j4 + 1], kmv.y, ap);
                cp = f2fma(MTr2[2 * j4],     kmv.x, cp);
                cp = f2fma(MTr2[2 * j4 + 1], kmv.y, cp);
            }
        }
        float rlo, rhi, alo, ahi, clo, chi;
        upk2(rp, rlo, rhi); upk2(ap, alo, ahi); upk2(cp, clo, chi);
        float rpart = rlo + rhi, apart = alo + ahi, cpart = clo + chi;
        rpart += __shfl_xor_sync(0xffffffffu, rpart, 1);
        apart += __shfl_xor_sync(0xffffffffu, apart, 1);
        cpart += __shfl_xor_sync(0xffffffffu, cpart, 1);
        const int pi = 4 * (i >> 1);
        if (!h) {
            S.rgdl[b2][gm1][pi + (i & 1)]     = sigm(apart + bgm);
            S.rgdl[b2][g]  [pi + 2 + (i & 1)] = S.raw[cur][g * 128 + 64 + i] - rpart;
        } else {
            S.cgkn[b4][gm1][pi + (i & 1)]     = sigm(cpart + bgm);
        }

        // ---- kn for row t+1 (warps 8-10) ----
        if (knw && t + 1 < T_STEPS) {
            float a0 = S.raw[(t + 1) & 7][kw * 128 + lane];
            float a1 = S.raw[(t + 1) & 7][kw * 128 + 32 + lane];
            float ssq = a0 * a0 + a1 * a1;
#pragma unroll
            for (int o = 16; o; o >>= 1) ssq += __shfl_xor_sync(0xffffffffu, ssq, o);
            float inv = __fdividef(1.0f, sqrtf(ssq) + 1e-6f);
            float k0 = a0 * inv, k1 = a1 * inv;
            S.kn[nb4][kw][lane]      = k0;
            S.kn[nb4][kw][lane + 32] = k1;
            S.cgkn[nb4][kw][4 * (lane >> 1) + 2 + (lane & 1)]        = k0;
            S.cgkn[nb4][kw][4 * ((lane + 32) >> 1) + 2 + (lane & 1)] = k1;
        }

        // ---- prefetch row t+4 (warps 4-7, flag poll cached) ----
        if (pf) {
            const int t4 = t + 4;
            if (t4 < T_STEPS) {
                const int r4 = t4 * BATCH + b;
                const int rb4 = r4 >> 6;
                if (rb4 > verified) {
                    while (ldacq(&g_cnt[rb4]) < 7) __nanosleep(64);
                    verified = rb4;
                }
                cp16(smem_u32(&S.raw[t4 & 7][pidx * 4]),
                     g_proj + (size_t)r4 * NPROJ + pidx * 4);
            }
            cp_commit();
            cp_wait1();
        }
        __syncthreads();

        // ---- region B: gated update + output ----
        const float cg_i = S.cgkn[b4][g][pi + (i & 1)];
        const float kn_i = S.cgkn[b4][g][pi + 2 + (i & 1)];
        const float rg_i = S.rgdl[b2][g][pi + (i & 1)];
        const float d_i  = S.rgdl[b2][g][pi + 2 + (i & 1)];
        const ull rgd = pk2(rg_i, rg_i), cgd = pk2(cg_i, cg_i);
        const ull dd  = pk2(d_i,  d_i),  knd = pk2(kn_i, kn_i);
        {
            const ulonglong2* ck = (const ulonglong2*)(S.cgkn[b4][g] + 64 * h);
            const ulonglong2* rd = (const ulonglong2*)(S.rgdl[b2][g] + 64 * h);
#pragma unroll
            for (int j = 0; j < 16; j++) {
                ulonglong2 a  = ck[j];
                ulonglong2 bq = rd[j];
                Mr2[j]  = f2fma(f2mul(Mr2[j],  a.x),  rgd, f2mul(a.y,  dd));
                MTr2[j] = f2fma(f2mul(MTr2[j], bq.x), cgd, f2mul(bq.y, knd));
            }
        }
        if (!g) {
            ull sq = 0ull;
            const ulonglong2* q2 = (const ulonglong2*)(S.raw[cur] + 384 + 32 * h);
#pragma unroll
            for (int j4 = 0; j4 < 8; j4++) {
                ulonglong2 q = q2[j4];
                sq = f2fma(Mr2[2 * j4],     q.x, sq);
                sq = f2fma(Mr2[2 * j4 + 1], q.y, sq);
            }
            float slo, shi; upk2(sq, slo, shi);
            float s = slo + shi;
            s += __shfl_xor_sync(0xffffffffu, s, 1);
            if (!h) out[((size_t)t * BATCH + b) * 64 + i] = s * sigm(s);
        }
    }

    if (write_M) {
        float* Mo = out + NOUT + ((size_t)(g * BATCH + b)) * 4096
                    + (size_t)i * 64 + 32 * h;
#pragma unroll
        for (int j = 0; j < 16; j++) {
            float a, c; upk2(Mr2[j], a, c);
            Mo[2 * j] = a; Mo[2 * j + 1] = c;
        }
    }
}

// ===========================================================================
// Variant B: 512 threads. Compute threads 0-383 identical; warps 12-15 are
// dedicated helpers (prefetch + kn-next). Used only if ptxas fits it with
// clear register headroom (numRegs <= 120 of the 128 cap) and no spills.
// ===========================================================================
__global__ __launch_bounds__(512, 1) void fused512(
    const float* __restrict__ X,
    const float* __restrict__ Wkv,
    const float* __restrict__ Wq,
    const float* __restrict__ Mi,
    const float* __restrict__ Bg,
    float* __restrict__ out,
    int write_M)
{
    __shared__ __align__(16) union { GemmS g; ScanS s; } sm;
    const int tid = threadIdx.x;

    if (blockIdx.x >= NSCAN) {
        gemm_body<512>(sm.g, tid, (int)blockIdx.x, X, Wkv, Wq);
        return;
    }

    const int b    = blockIdx.x;
    const bool cmp = (tid < 384);
    const int g    = tid >> 7;           // valid for cmp
    const int r    = tid & 127;
    const int i    = r >> 1;
    const int h    = tid & 1;
    const int gm1  = (g + 2) % 3;
    const int wid  = tid >> 5, lane = tid & 31;
    ScanS& S = sm.s;

    ull Mr2[16], MTr2[16];
    if (cmp) {
        const float* M0 = Mi + ((size_t)(g * BATCH + b)) * 4096;
#pragma unroll
        for (int j = 0; j < 16; j++) {
            float2 a = *(const float2*)&M0[i * 64 + 32 * h + 2 * j];
            Mr2[j]  = pk2(a.x, a.y);
            MTr2[j] = pk2(M0[(32 * h + 2 * j) * 64 + i],
                          M0[(32 * h + 2 * j + 1) * 64 + i]);
        }
    }
    const float bgm = Bg[gm1 * 64 + i];

    const bool pf   = (tid >= 384 && tid < 496);  // helper warps 12-15
    const int  pidx = tid - 384;
    const bool knw  = (wid >= 12 && wid < 15);    // helper warps 12-14
    const int  kw   = wid - 12;
    int verified = 0;

    if (pf) {
        while (ldacq(&g_cnt[0]) < 7) __nanosleep(64);
#pragma unroll
        for (int rr = 0; rr < 3; rr++) {
            cp16(smem_u32(&S.raw[rr][pidx * 4]),
                 g_proj + (size_t)(rr * BATCH + b) * NPROJ + pidx * 4);
            cp_commit();
        }
        cp16(smem_u32(&S.raw[3][pidx * 4]),
             g_proj + (size_t)(3 * BATCH + b) * NPROJ + pidx * 4);
        cp_commit();
        cp_wait1();
    }
    __syncthreads();
    if (knw) {
        float a0 = S.raw[0][kw * 128 + lane];
        float a1 = S.raw[0][kw * 128 + 32 + lane];
        float ssq = a0 * a0 + a1 * a1;
#pragma unroll
        for (int o = 16; o; o >>= 1) ssq += __shfl_xor_sync(0xffffffffu, ssq, o);
        float inv = __fdividef(1.0f, sqrtf(ssq) + 1e-6f);
        float k0 = a0 * inv, k1 = a1 * inv;
        S.kn[0][kw][lane]      = k0;
        S.kn[0][kw][lane + 32] = k1;
        S.cgkn[0][kw][4 * (lane >> 1) + 2 + (lane & 1)]        = k0;
        S.cgkn[0][kw][4 * ((lane + 32) >> 1) + 2 + (lane & 1)] = k1;
    }
    __syncthreads();

    for (int t = 0; t < T_STEPS; t++) {
        const int cur = t & 7, b4 = t & 3, b2 = t & 1;
        const int nb4 = (t + 1) & 3;
        const int pi = 4 * (i >> 1);

        if (cmp) {
            // ---- dots + gates ----
            ull rp = 0ull, ap = 0ull, cp = 0ull;
            const ulonglong2* kg = (const ulonglong2*)(S.kn[b4][g]   + 32 * h);
            const ulonglong2* km = (const ulonglong2*)(S.kn[b4][gm1] + 32 * h);
#pragma unroll
            for (int j4 = 0; j4 < 8; j4++) {
                ulonglong2 kv  = kg[j4];
                ulonglong2 kmv = km[j4];
                rp = f2fma(Mr2[2 * j4],     kv.x,  rp);
                rp = f2fma(Mr2[2 * j4 + 1], kv.y,  rp);
                ap = f2fma(Mr2[2 * j4],     kmv.x, ap);
                ap = f2fma(Mr2[2 * j4 + 1], kmv.y, ap);
                cp = f2fma(MTr2[2 * j4],     kmv.x, cp);
                cp = f2fma(MTr2[2 * j4 + 1], kmv.y, cp);
            }
            float rlo, rhi, alo, ahi, clo, chi;
            upk2(rp, rlo, rhi); upk2(ap, alo, ahi); upk2(cp, clo, chi);
            float rpart = rlo + rhi, apart = alo + ahi, cpart = clo + chi;
            rpart += __shfl_xor_sync(0xffffffffu, rpart, 1);
            apart += __shfl_xor_sync(0xffffffffu, apart, 1);
            cpart += __shfl_xor_sync(0xffffffffu, cpart, 1);
            if (!h) {
                S.rgdl[b2][gm1][pi + (i & 1)]     = sigm(apart + bgm);
                S.rgdl[b2][g]  [pi + 2 + (i & 1)] = S.raw[cur][g * 128 + 64 + i] - rpart;
            } else {
                S.cgkn[b4][gm1][pi + (i & 1)]     = sigm(cpart + bgm);
            }
        } else {
            // ---- helpers: prefetch first (memory in flight), then kn-next
            if (pf) {
                const int t4 = t + 4;
                if (t4 < T_STEPS) {
                    const int r4 = t4 * BATCH + b;
                    const int rb4 = r4 >> 6;
                    if (rb4 > verified) {
                        while (ldacq(&g_cnt[rb4]) < 7) __nanosleep(64);
                        verified = rb4;
                    }
                    cp16(smem_u32(&S.raw[t4 & 7][pidx * 4]),
                         g_proj + (size_t)r4 * NPROJ + pidx * 4);
                }
                cp_commit();
            }
            if (knw && t + 1 < T_STEPS) {
                float a0 = S.raw[(t + 1) & 7][kw * 128 + lane];
                float a1 = S.raw[(t + 1) & 7][kw * 128 + 32 + lane];
                float ssq = a0 * a0 + a1 * a1;
#pragma unroll
                for (int o = 16; o; o >>= 1)
                    ssq += __shfl_xor_sync(0xffffffffu, ssq, o);
                float inv = __fdividef(1.0f, sqrtf(ssq) + 1e-6f);
                float k0 = a0 * inv, k1 = a1 * inv;
                S.kn[nb4][kw][lane]      = k0;
                S.kn[nb4][kw][lane + 32] = k1;
                S.cgkn[nb4][kw][4 * (lane >> 1) + 2 + (lane & 1)]        = k0;
                S.cgkn[nb4][kw][4 * ((lane + 32) >> 1) + 2 + (lane & 1)] = k1;
            }
            if (pf) cp_wait1();
        }
        __syncthreads();

        if (cmp) {
            const float cg_i = S.cgkn[b4][g][pi + (i & 1)];
            const float kn_i = S.cgkn[b4][g][pi + 2 + (i & 1)];
            const float rg_i = S.rgdl[b2][g][pi + (i & 1)];
            const float d_i  = S.rgdl[b2][g][pi + 2 + (i & 1)];
            const ull rgd = pk2(rg_i, rg_i), cgd = pk2(cg_i, cg_i);
            const ull dd  = pk2(d_i,  d_i),  knd = pk2(kn_i, kn_i);
            const ulonglong2* ck = (const ulonglong2*)(S.cgkn[b4][g] + 64 * h);
            const ulonglong2* rd = (const ulonglong2*)(S.rgdl[b2][g] + 64 * h);
#pragma unroll
            for (int j = 0; j < 16; j++) {
                ulonglong2 a  = ck[j];
                ulonglong2 bq = rd[j];
                Mr2[j]  = f2fma(f2mul(Mr2[j],  a.x),  rgd, f2mul(a.y,  dd));
                MTr2[j] = f2fma(f2mul(MTr2[j], bq.x), cgd, f2mul(bq.y, knd));
            }
            if (!g) {
                ull sq = 0ull;
                const ulonglong2* q2 = (const ulonglong2*)(S.raw[cur] + 384 + 32 * h);
#pragma unroll
                for (int j4 = 0; j4 < 8; j4++) {
                    ulonglong2 q = q2[j4];
                    sq = f2fma(Mr2[2 * j4],     q.x, sq);
                    sq = f2fma(Mr2[2 * j4 + 1], q.y, sq);
                }
                float slo, shi; upk2(sq, slo, shi);
                float s = slo + shi;
                s += __shfl_xor_sync(0xffffffffu, s, 1);
                if (!h) out[((size_t)t * BATCH + b) * 64 + i] = s * sigm(s);
            }
        }
    }

    if (cmp && write_M) {
        float* Mo = out + NOUT + ((size_t)(g * BATCH + b)) * 4096
                    + (size_t)i * 64 + 32 * h;
#pragma unroll
        for (int j = 0; j < 16; j++) {
            float a, c; upk2(Mr2[j], a, c);
            Mo[2 * j] = a; Mo[2 * j + 1] = c;
        }
    }
}

// ---------------------------------------------------------------------------
extern "C" void kernel_launch(void* const* d_in, const int* in_sizes, int n_in,
                              void* d_out, int out_size)
{
    const float *x = nullptr, *Mi = nullptr, *Wkv = nullptr,
                *Wq = nullptr, *Bg = nullptr;
    for (int idx = 0; idx < n_in; idx++) {
        switch (in_sizes[idx]) {
            case 33554432: x   = (const float*)d_in[idx]; break;
            case 196608:   Mi  = (const float*)d_in[idx]; break;
            case 393216:   Wkv = (const float*)d_in[idx]; break;
            case 65536:    Wq  = (const float*)d_in[idx]; break;
            case 192:      Bg  = (const float*)d_in[idx]; break;
        }
    }
    if (!x || !Mi || !Wkv || !Wq || !Bg) {
        x   = (const float*)d_in[0];
        Mi  = (const float*)d_in[1];
        Wkv = (const float*)d_in[2];
        Wq  = (const float*)d_in[3];
        Bg  = (const float*)d_in[4];
    }

    const int write_M = (out_size >= NOUT + MSIZE) ? 1 : 0;

    // Guard: use the 512 variant only if ptxas left clear register headroom
    // (at-cap numRegs == rematerialization cliff, see R7 post-mortem) and no
    // spills. Otherwise the improved 384 variant.
    cudaFuncAttributes attr;
    bool use512 = false;
    if (cudaFuncGetAttributes(&attr, (const void*)fused512) == cudaSuccess)
        use512 = (attr.localSizeBytes == 0 && attr.numRegs > 0 &&
                  attr.numRegs <= 120);

    zero_cnt<<<1, 512>>>();
    if (use512)
        fused512<<<NCTA, 512>>>(x, Wkv, Wq, Mi, Bg, (float*)d_out, write_M);
    else
        fused384<<<NCTA, 384>>>(x, Wkv, Wq, Mi, Bg, (float*)d_out, write_M);
}